// round 2
// baseline (speedup 1.0000x reference)
#include <cuda_runtime.h>
#include <cuda_bf16.h>
#include <math_constants.h>

#define FULL 0xffffffffu

static constexpr int B = 8;
static constexpr int N = 4096;
static constexpr int C = 128;
static constexpr int KNN = 16;

// scratch (device globals: no allocation allowed)
__device__ float  g_zbn[B * N * C];    // zbn[b][n][c], n-major rows of 512B
__device__ float4 g_xyz4[B * N];       // (x,y,z,|p|^2)
__device__ int    g_idx[B * N * KNN];  // 16 NN indices per query

// ---------------------------------------------------------------------------
// Kernel 0: pack xyz + squared norm into float4
// ---------------------------------------------------------------------------
__global__ void prep_kernel(const float* __restrict__ xyz)
{
    int i = blockIdx.x * 256 + threadIdx.x;   // over B*N
    float x = xyz[3 * i], y = xyz[3 * i + 1], z = xyz[3 * i + 2];
    g_xyz4[i] = make_float4(x, y, z, x * x + y * y + z * z);
}

// ---------------------------------------------------------------------------
// Kernel 1: zbn[b][n][c] = relu(scale_c * (sum_k W[c][k] * x[b][k][n]) + bias_c)
// ---------------------------------------------------------------------------
__global__ __launch_bounds__(256) void gemm_bn_relu_kernel(
    const float* __restrict__ x,      // [B][C][N]
    const float* __restrict__ W,      // [C_out][C_in]
    const float* __restrict__ gamma,
    const float* __restrict__ beta,
    const float* __restrict__ rmean,
    const float* __restrict__ rvar)
{
    __shared__ float xs[32][64];    // [k][n]
    __shared__ float ws[32][128];   // [k][c], XOR-swizzled in 4-float units

    const int b  = blockIdx.y;
    const int n0 = blockIdx.x * 64;
    const int tid = threadIdx.x;
    const int tc = tid & 31;
    const int tn = tid >> 5;

    float acc[4][8];
#pragma unroll
    for (int j = 0; j < 4; ++j)
#pragma unroll
        for (int i = 0; i < 8; ++i) acc[j][i] = 0.0f;

    const float* xb = x + (size_t)b * C * N;

    for (int k0 = 0; k0 < C; k0 += 32) {
#pragma unroll
        for (int i = tid; i < 32 * 64; i += 256) {
            int kk = i >> 6, nn = i & 63;
            xs[kk][nn] = xb[(size_t)(k0 + kk) * N + n0 + nn];
        }
#pragma unroll
        for (int i = tid; i < 32 * 128; i += 256) {
            int c = i >> 5, kk = i & 31;
            ws[kk][c ^ ((kk & 7) << 2)] = W[c * C + k0 + kk];
        }
        __syncthreads();

#pragma unroll
        for (int kk = 0; kk < 32; ++kk) {
            float4 wv  = *(const float4*)&ws[kk][((tc ^ (kk & 7)) << 2)];
            float4 xv0 = *(const float4*)&xs[kk][tn * 8];
            float4 xv1 = *(const float4*)&xs[kk][tn * 8 + 4];
            float wj[4] = {wv.x, wv.y, wv.z, wv.w};
            float xi[8] = {xv0.x, xv0.y, xv0.z, xv0.w, xv1.x, xv1.y, xv1.z, xv1.w};
#pragma unroll
            for (int j = 0; j < 4; ++j)
#pragma unroll
                for (int i = 0; i < 8; ++i)
                    acc[j][i] = fmaf(wj[j], xi[i], acc[j][i]);
        }
        __syncthreads();
    }

    const int c0 = tc * 4;
    float sc[4], bi[4];
#pragma unroll
    for (int j = 0; j < 4; ++j) {
        sc[j] = gamma[c0 + j] * rsqrtf(rvar[c0 + j] + 1e-5f);
        bi[j] = beta[c0 + j] - rmean[c0 + j] * sc[j];
    }
#pragma unroll
    for (int i = 0; i < 8; ++i) {
        int n = n0 + tn * 8 + i;
        float4 o;
        o.x = fmaxf(fmaf(acc[0][i], sc[0], bi[0]), 0.0f);
        o.y = fmaxf(fmaf(acc[1][i], sc[1], bi[1]), 0.0f);
        o.z = fmaxf(fmaf(acc[2][i], sc[2], bi[2]), 0.0f);
        o.w = fmaxf(fmaf(acc[3][i], sc[3], bi[3]), 0.0f);
        *(float4*)&g_zbn[((size_t)b * N + n) * C + c0] = o;
    }
}

// ---------------------------------------------------------------------------
// Kernel 2: thread-per-query exact top-16. Sorted 16-reg list + deferred
// smem accept-buffer with warp-synchronous flush (aligns all lanes' inserts).
// Block: 128 threads = 128 queries. Grid: (N/128, B).
// ---------------------------------------------------------------------------
__device__ __forceinline__ void insert16(float (&tv)[16], int (&ti)[16],
                                         float e, int jj)
{
#pragma unroll
    for (int t = 15; t >= 0; --t) {
        bool gt  = tv[t] > e;
        bool gtp = (t > 0) && (tv[t - 1] > e);
        float nv = gtp ? tv[t - 1] : e;
        int   ni = gtp ? ti[t - 1] : jj;
        if (gt) { tv[t] = nv; ti[t] = ni; }
    }
}

__global__ __launch_bounds__(128) void knn_kernel()
{
    __shared__ float bE[16][128];
    __shared__ int   bI[16][128];

    const int tid = threadIdx.x;
    const int b   = blockIdx.y;
    const int q   = blockIdx.x * 128 + tid;

    const float4* __restrict__ xb = g_xyz4 + (size_t)b * N;
    const float4 Q = xb[q];

    float tv[16]; int ti[16];
#pragma unroll
    for (int t = 0; t < 16; ++t) { tv[t] = CUDART_INF_F; ti[t] = 0; }
    int   cnt = 0;
    float thr = CUDART_INF_F;

    for (int j0 = 0; j0 < N; j0 += 8) {
#pragma unroll
        for (int u = 0; u < 8; ++u) {
            int j = j0 + u;
            float4 p = __ldg(&xb[j]);
            float dot = Q.x * p.x;
            dot = fmaf(Q.y, p.y, dot);
            dot = fmaf(Q.z, p.z, dot);
            float e = fmaf(-2.0f, dot, p.w);   // ranks same as s_i+s_j-2dot
            if (e < thr) { bE[cnt][tid] = e; bI[cnt][tid] = j; cnt++; }
        }
        if (__any_sync(FULL, cnt >= 8)) {
            int mx = cnt;
#pragma unroll
            for (int o = 16; o; o >>= 1) mx = max(mx, __shfl_xor_sync(FULL, mx, o));
            for (int s = 0; s < mx; ++s) {
                float e = (s < cnt) ? bE[s][tid] : CUDART_INF_F;
                int  jj = (s < cnt) ? bI[s][tid] : 0;
                if (__any_sync(FULL, e < tv[15]))
                    insert16(tv, ti, e, jj);
            }
            cnt = 0;
            thr = tv[15];
        }
    }
    // final flush
    {
        int mx = cnt;
#pragma unroll
        for (int o = 16; o; o >>= 1) mx = max(mx, __shfl_xor_sync(FULL, mx, o));
        for (int s = 0; s < mx; ++s) {
            float e = (s < cnt) ? bE[s][tid] : CUDART_INF_F;
            int  jj = (s < cnt) ? bI[s][tid] : 0;
            if (__any_sync(FULL, e < tv[15]))
                insert16(tv, ti, e, jj);
        }
    }

    int* op = g_idx + ((size_t)b * N + q) * KNN;
#pragma unroll
    for (int t = 0; t < 16; ++t) op[t] = ti[t];
}

// ---------------------------------------------------------------------------
// Kernel 3: gather-max over 16 neighbors + transpose to [B][C][N].
// Warp per query (4 queries/warp), 256 threads. Grid: (N/32, B).
// ---------------------------------------------------------------------------
__global__ __launch_bounds__(256) void gather_kernel(float* __restrict__ out)
{
    __shared__ float sout[128][33];

    const int b    = blockIdx.y;
    const int n0   = blockIdx.x * 32;
    const int tid  = threadIdx.x;
    const int w    = tid >> 5;
    const int lane = tid & 31;

    const float* __restrict__ zb = g_zbn + (size_t)b * N * C;

    for (int s = 0; s < 4; ++s) {
        const int ql = w * 4 + s;
        const int n  = n0 + ql;
        int myidx = (lane < 16) ? g_idx[((size_t)b * N + n) * KNN + lane] : 0;

        float m0 = 0.0f, m1 = 0.0f, m2 = 0.0f, m3 = 0.0f;  // post-ReLU >= 0
#pragma unroll
        for (int t = 0; t < KNN; t += 2) {
            int j1 = __shfl_sync(FULL, myidx, t);
            int j2 = __shfl_sync(FULL, myidx, t + 1);
            const float* c1 = zb + ((size_t)j1 << 7);
            const float* c2 = zb + ((size_t)j2 << 7);
            float a0 = c1[lane], a1 = c1[lane + 32], a2 = c1[lane + 64], a3 = c1[lane + 96];
            float b0 = c2[lane], b1 = c2[lane + 32], b2 = c2[lane + 64], b3 = c2[lane + 96];
            m0 = fmaxf(m0, fmaxf(a0, b0));
            m1 = fmaxf(m1, fmaxf(a1, b1));
            m2 = fmaxf(m2, fmaxf(a2, b2));
            m3 = fmaxf(m3, fmaxf(a3, b3));
        }

        sout[lane][ql]      = m0;
        sout[lane + 32][ql] = m1;
        sout[lane + 64][ql] = m2;
        sout[lane + 96][ql] = m3;
    }
    __syncthreads();

    float* ob = out + (size_t)b * C * N + n0;
    for (int i = tid; i < 128 * 32; i += 256) {
        int c = i >> 5, nn = i & 31;
        ob[(size_t)c * N + nn] = sout[c][nn];
    }
}

// ---------------------------------------------------------------------------
extern "C" void kernel_launch(void* const* d_in, const int* in_sizes, int n_in,
                              void* d_out, int out_size)
{
    const float* xyz   = (const float*)d_in[0];
    const float* x     = (const float*)d_in[1];
    const float* W     = (const float*)d_in[2];
    const float* gamma = (const float*)d_in[3];
    const float* beta  = (const float*)d_in[4];
    const float* rmean = (const float*)d_in[5];
    const float* rvar  = (const float*)d_in[6];
    float* out = (float*)d_out;

    prep_kernel<<<B * N / 256, 256>>>(xyz);
    gemm_bn_relu_kernel<<<dim3(N / 64, B), 256>>>(x, W, gamma, beta, rmean, rvar);
    knn_kernel<<<dim3(N / 128, B), 128>>>();
    gather_kernel<<<dim3(N / 32, B), 256>>>(out);
}

// round 3
// speedup vs baseline: 1.3492x; 1.3492x over previous
#include <cuda_runtime.h>
#include <cuda_bf16.h>
#include <math_constants.h>

#define FULL 0xffffffffu

static constexpr int B = 8;
static constexpr int N = 4096;
static constexpr int C = 128;
static constexpr int KNN = 16;

// scratch (device globals: no allocation allowed)
__device__ float  g_zbn[B * N * C];    // zbn[b][n][c], n-major rows of 512B
__device__ float4 g_xyz4[B * N];       // (x,y,z,|p|^2)
__device__ int    g_idx[B * N * KNN];  // 16 NN indices per query

// ---------------------------------------------------------------------------
// Kernel 0: pack xyz + squared norm into float4
// ---------------------------------------------------------------------------
__global__ void prep_kernel(const float* __restrict__ xyz)
{
    int i = blockIdx.x * 256 + threadIdx.x;   // over B*N
    float x = xyz[3 * i], y = xyz[3 * i + 1], z = xyz[3 * i + 2];
    g_xyz4[i] = make_float4(x, y, z, x * x + y * y + z * z);
}

// ---------------------------------------------------------------------------
// Kernel 1: zbn[b][n][c] = relu(scale_c * (sum_k W[c][k] * x[b][k][n]) + bias_c)
// ---------------------------------------------------------------------------
__global__ __launch_bounds__(256) void gemm_bn_relu_kernel(
    const float* __restrict__ x,      // [B][C][N]
    const float* __restrict__ W,      // [C_out][C_in]
    const float* __restrict__ gamma,
    const float* __restrict__ beta,
    const float* __restrict__ rmean,
    const float* __restrict__ rvar)
{
    __shared__ float xs[32][64];    // [k][n]
    __shared__ float ws[32][128];   // [k][c], XOR-swizzled in 4-float units

    const int b  = blockIdx.y;
    const int n0 = blockIdx.x * 64;
    const int tid = threadIdx.x;
    const int tc = tid & 31;
    const int tn = tid >> 5;

    float acc[4][8];
#pragma unroll
    for (int j = 0; j < 4; ++j)
#pragma unroll
        for (int i = 0; i < 8; ++i) acc[j][i] = 0.0f;

    const float* xb = x + (size_t)b * C * N;

    for (int k0 = 0; k0 < C; k0 += 32) {
#pragma unroll
        for (int i = tid; i < 32 * 64; i += 256) {
            int kk = i >> 6, nn = i & 63;
            xs[kk][nn] = xb[(size_t)(k0 + kk) * N + n0 + nn];
        }
#pragma unroll
        for (int i = tid; i < 32 * 128; i += 256) {
            int c = i >> 5, kk = i & 31;
            ws[kk][c ^ ((kk & 7) << 2)] = W[c * C + k0 + kk];
        }
        __syncthreads();

#pragma unroll
        for (int kk = 0; kk < 32; ++kk) {
            float4 wv  = *(const float4*)&ws[kk][((tc ^ (kk & 7)) << 2)];
            float4 xv0 = *(const float4*)&xs[kk][tn * 8];
            float4 xv1 = *(const float4*)&xs[kk][tn * 8 + 4];
            float wj[4] = {wv.x, wv.y, wv.z, wv.w};
            float xi[8] = {xv0.x, xv0.y, xv0.z, xv0.w, xv1.x, xv1.y, xv1.z, xv1.w};
#pragma unroll
            for (int j = 0; j < 4; ++j)
#pragma unroll
                for (int i = 0; i < 8; ++i)
                    acc[j][i] = fmaf(wj[j], xi[i], acc[j][i]);
        }
        __syncthreads();
    }

    const int c0 = tc * 4;
    float sc[4], bi[4];
#pragma unroll
    for (int j = 0; j < 4; ++j) {
        sc[j] = gamma[c0 + j] * rsqrtf(rvar[c0 + j] + 1e-5f);
        bi[j] = beta[c0 + j] - rmean[c0 + j] * sc[j];
    }
#pragma unroll
    for (int i = 0; i < 8; ++i) {
        int n = n0 + tn * 8 + i;
        float4 o;
        o.x = fmaxf(fmaf(acc[0][i], sc[0], bi[0]), 0.0f);
        o.y = fmaxf(fmaf(acc[1][i], sc[1], bi[1]), 0.0f);
        o.z = fmaxf(fmaf(acc[2][i], sc[2], bi[2]), 0.0f);
        o.w = fmaxf(fmaf(acc[3][i], sc[3], bi[3]), 0.0f);
        *(float4*)&g_zbn[((size_t)b * N + n) * C + c0] = o;
    }
}

// ---------------------------------------------------------------------------
// Kernel 2: thread-per-query exact top-16.
// Sorted 16-reg list; accepts deferred into a per-thread smem buffer and
// flushed warp-synchronously so all lanes' inserts co-execute.
// Distance uses the EXACT round-1 formula (qs + p.w then fused -2*dot) to
// keep tie behavior / rel_err at ~1e-7.
// Block: 64 threads = 64 queries. Grid: (N/64, B) = 512 blocks.
// ---------------------------------------------------------------------------
__device__ __forceinline__ void insert16(float (&tv)[16], int (&ti)[16],
                                         float e, int jj)
{
#pragma unroll
    for (int t = 15; t >= 0; --t) {
        bool gt  = tv[t] > e;                   // strict: ties keep incumbent
        bool gtp = (t > 0) && (tv[t - 1] > e);
        float nv = gtp ? tv[t - 1] : e;
        int   ni = gtp ? ti[t - 1] : jj;
        if (gt) { tv[t] = nv; ti[t] = ni; }
    }
}

__global__ __launch_bounds__(64) void knn_kernel()
{
    __shared__ float bE[16][64];
    __shared__ int   bI[16][64];

    const int tid = threadIdx.x;
    const int b   = blockIdx.y;
    const int q   = blockIdx.x * 64 + tid;

    const float4* __restrict__ xb = g_xyz4 + (size_t)b * N;
    const float4 Q = xb[q];
    const float qs = Q.w;

    float tv[16]; int ti[16];
#pragma unroll
    for (int t = 0; t < 16; ++t) { tv[t] = CUDART_INF_F; ti[t] = 0; }

    // ---- seed: first 32 candidates, unconditional co-executed inserts ----
#pragma unroll
    for (int j = 0; j < 32; ++j) {
        float4 p = __ldg(&xb[j]);
        float dot = Q.x * p.x;
        dot = fmaf(Q.y, p.y, dot);
        dot = fmaf(Q.z, p.z, dot);
        float d = fmaf(-2.0f, dot, qs + p.w);
        insert16(tv, ti, d, j);
    }
    float thr = tv[15];
    int   cnt = 0;

    // ---- main scan ----
    for (int j0 = 32; j0 < N; j0 += 8) {
#pragma unroll
        for (int u = 0; u < 8; ++u) {
            int j = j0 + u;
            float4 p = __ldg(&xb[j]);
            float dot = Q.x * p.x;
            dot = fmaf(Q.y, p.y, dot);
            dot = fmaf(Q.z, p.z, dot);
            float d = fmaf(-2.0f, dot, qs + p.w);
            if (d < thr) { bE[cnt][tid] = d; bI[cnt][tid] = j; cnt++; }
        }
        if (__any_sync(FULL, cnt >= 8)) {
            int mx = __reduce_max_sync(FULL, cnt);
            for (int s = 0; s < mx; ++s) {
                float e = (s < cnt) ? bE[s][tid] : CUDART_INF_F;
                int  jj = (s < cnt) ? bI[s][tid] : 0;
                insert16(tv, ti, e, jj);
            }
            cnt = 0;
            thr = tv[15];
        }
    }
    // ---- final flush ----
    if (__any_sync(FULL, cnt > 0)) {
        int mx = __reduce_max_sync(FULL, cnt);
        for (int s = 0; s < mx; ++s) {
            float e = (s < cnt) ? bE[s][tid] : CUDART_INF_F;
            int  jj = (s < cnt) ? bI[s][tid] : 0;
            insert16(tv, ti, e, jj);
        }
    }

    int* op = g_idx + ((size_t)b * N + q) * KNN;
#pragma unroll
    for (int t = 0; t < 16; ++t) op[t] = ti[t];
}

// ---------------------------------------------------------------------------
// Kernel 3: gather-max over 16 neighbors + transpose to [B][C][N].
// Warp per query (4 queries/warp), 256 threads. Grid: (N/32, B).
// ---------------------------------------------------------------------------
__global__ __launch_bounds__(256) void gather_kernel(float* __restrict__ out)
{
    __shared__ float sout[128][33];

    const int b    = blockIdx.y;
    const int n0   = blockIdx.x * 32;
    const int tid  = threadIdx.x;
    const int w    = tid >> 5;
    const int lane = tid & 31;

    const float* __restrict__ zb = g_zbn + (size_t)b * N * C;

    for (int s = 0; s < 4; ++s) {
        const int ql = w * 4 + s;
        const int n  = n0 + ql;
        int myidx = (lane < 16) ? g_idx[((size_t)b * N + n) * KNN + lane] : 0;

        float m0 = 0.0f, m1 = 0.0f, m2 = 0.0f, m3 = 0.0f;  // post-ReLU >= 0
#pragma unroll
        for (int t = 0; t < KNN; t += 2) {
            int j1 = __shfl_sync(FULL, myidx, t);
            int j2 = __shfl_sync(FULL, myidx, t + 1);
            const float* c1 = zb + ((size_t)j1 << 7);
            const float* c2 = zb + ((size_t)j2 << 7);
            float a0 = c1[lane], a1 = c1[lane + 32], a2 = c1[lane + 64], a3 = c1[lane + 96];
            float b0 = c2[lane], b1 = c2[lane + 32], b2 = c2[lane + 64], b3 = c2[lane + 96];
            m0 = fmaxf(m0, fmaxf(a0, b0));
            m1 = fmaxf(m1, fmaxf(a1, b1));
            m2 = fmaxf(m2, fmaxf(a2, b2));
            m3 = fmaxf(m3, fmaxf(a3, b3));
        }

        sout[lane][ql]      = m0;
        sout[lane + 32][ql] = m1;
        sout[lane + 64][ql] = m2;
        sout[lane + 96][ql] = m3;
    }
    __syncthreads();

    float* ob = out + (size_t)b * C * N + n0;
    for (int i = tid; i < 128 * 32; i += 256) {
        int c = i >> 5, nn = i & 31;
        ob[(size_t)c * N + nn] = sout[c][nn];
    }
}

// ---------------------------------------------------------------------------
extern "C" void kernel_launch(void* const* d_in, const int* in_sizes, int n_in,
                              void* d_out, int out_size)
{
    const float* xyz   = (const float*)d_in[0];
    const float* x     = (const float*)d_in[1];
    const float* W     = (const float*)d_in[2];
    const float* gamma = (const float*)d_in[3];
    const float* beta  = (const float*)d_in[4];
    const float* rmean = (const float*)d_in[5];
    const float* rvar  = (const float*)d_in[6];
    float* out = (float*)d_out;

    prep_kernel<<<B * N / 256, 256>>>(xyz);
    gemm_bn_relu_kernel<<<dim3(N / 64, B), 256>>>(x, W, gamma, beta, rmean, rvar);
    knn_kernel<<<dim3(N / 64, B), 64>>>();
    gather_kernel<<<dim3(N / 32, B), 256>>>(out);
}

// round 4
// speedup vs baseline: 2.3996x; 1.7786x over previous
#include <cuda_runtime.h>
#include <cuda_bf16.h>
#include <math_constants.h>

#define FULL 0xffffffffu

static constexpr int B = 8;
static constexpr int N = 4096;
static constexpr int C = 128;
static constexpr int KNN = 16;

// scratch (device globals: no allocation allowed)
__device__ float  g_zbn[B * N * C];    // zbn[b][n][c], n-major rows of 512B
__device__ float4 g_xyz4[B * N];       // (x,y,z,|p|^2)
__device__ int    g_idx[B * N * KNN];  // 16 NN indices per query

// ---------------------------------------------------------------------------
// Kernel 0: pack xyz + squared norm into float4
// ---------------------------------------------------------------------------
__global__ void prep_kernel(const float* __restrict__ xyz)
{
    int i = blockIdx.x * 256 + threadIdx.x;   // over B*N
    float x = xyz[3 * i], y = xyz[3 * i + 1], z = xyz[3 * i + 2];
    g_xyz4[i] = make_float4(x, y, z, x * x + y * y + z * z);
}

// ---------------------------------------------------------------------------
// Kernel 1: zbn[b][n][c] = relu(scale_c * (sum_k W[c][k] * x[b][k][n]) + bias_c)
// ---------------------------------------------------------------------------
__global__ __launch_bounds__(256) void gemm_bn_relu_kernel(
    const float* __restrict__ x,      // [B][C][N]
    const float* __restrict__ W,      // [C_out][C_in]
    const float* __restrict__ gamma,
    const float* __restrict__ beta,
    const float* __restrict__ rmean,
    const float* __restrict__ rvar)
{
    __shared__ float xs[32][64];    // [k][n]
    __shared__ float ws[32][128];   // [k][c], XOR-swizzled in 4-float units

    const int b  = blockIdx.y;
    const int n0 = blockIdx.x * 64;
    const int tid = threadIdx.x;
    const int tc = tid & 31;
    const int tn = tid >> 5;

    float acc[4][8];
#pragma unroll
    for (int j = 0; j < 4; ++j)
#pragma unroll
        for (int i = 0; i < 8; ++i) acc[j][i] = 0.0f;

    const float* xb = x + (size_t)b * C * N;

    for (int k0 = 0; k0 < C; k0 += 32) {
#pragma unroll
        for (int i = tid; i < 32 * 64; i += 256) {
            int kk = i >> 6, nn = i & 63;
            xs[kk][nn] = xb[(size_t)(k0 + kk) * N + n0 + nn];
        }
#pragma unroll
        for (int i = tid; i < 32 * 128; i += 256) {
            int c = i >> 5, kk = i & 31;
            ws[kk][c ^ ((kk & 7) << 2)] = W[c * C + k0 + kk];
        }
        __syncthreads();

#pragma unroll
        for (int kk = 0; kk < 32; ++kk) {
            float4 wv  = *(const float4*)&ws[kk][((tc ^ (kk & 7)) << 2)];
            float4 xv0 = *(const float4*)&xs[kk][tn * 8];
            float4 xv1 = *(const float4*)&xs[kk][tn * 8 + 4];
            float wj[4] = {wv.x, wv.y, wv.z, wv.w};
            float xi[8] = {xv0.x, xv0.y, xv0.z, xv0.w, xv1.x, xv1.y, xv1.z, xv1.w};
#pragma unroll
            for (int j = 0; j < 4; ++j)
#pragma unroll
                for (int i = 0; i < 8; ++i)
                    acc[j][i] = fmaf(wj[j], xi[i], acc[j][i]);
        }
        __syncthreads();
    }

    const int c0 = tc * 4;
    float sc[4], bi[4];
#pragma unroll
    for (int j = 0; j < 4; ++j) {
        sc[j] = gamma[c0 + j] * rsqrtf(rvar[c0 + j] + 1e-5f);
        bi[j] = beta[c0 + j] - rmean[c0 + j] * sc[j];
    }
#pragma unroll
    for (int i = 0; i < 8; ++i) {
        int n = n0 + tn * 8 + i;
        float4 o;
        o.x = fmaxf(fmaf(acc[0][i], sc[0], bi[0]), 0.0f);
        o.y = fmaxf(fmaf(acc[1][i], sc[1], bi[1]), 0.0f);
        o.z = fmaxf(fmaf(acc[2][i], sc[2], bi[2]), 0.0f);
        o.w = fmaxf(fmaf(acc[3][i], sc[3], bi[3]), 0.0f);
        *(float4*)&g_zbn[((size_t)b * N + n) * C + c0] = o;
    }
}

// ---------------------------------------------------------------------------
// Kernel 2: top-16 KNN, thread-per-(query,split).
// Branch-free accept path: setp + predicated STS.64 + predicated add (asm).
// 128-thread block = 64 queries x 2 candidate splits; split-1 merges into
// split-0 through smem at the end. Distance formula bit-identical to ref path.
// Grid: (N/64, B) = 512 blocks.
// ---------------------------------------------------------------------------
__device__ __forceinline__ void insert16(float (&tv)[16], int (&ti)[16],
                                         float e, int jj)
{
#pragma unroll
    for (int t = 15; t >= 0; --t) {
        bool gt  = tv[t] > e;                   // strict: ties keep incumbent
        bool gtp = (t > 0) && (tv[t - 1] > e);
        float nv = gtp ? tv[t - 1] : e;
        int   ni = gtp ? ti[t - 1] : jj;
        if (gt) { tv[t] = nv; ti[t] = ni; }
    }
}

__global__ __launch_bounds__(128) void knn_kernel()
{
    __shared__ unsigned long long buf[16][128];  // accept buffer, 16KB
    __shared__ float mD[64][17];                 // merge staging (pad: no bank conflict)
    __shared__ int   mI[64][17];

    const int tid = threadIdx.x;
    const int u   = tid & 63;
    const int s   = tid >> 6;                    // split 0/1 (warp-homogeneous)
    const int b   = blockIdx.y;
    const int q   = blockIdx.x * 64 + u;

    const float4* __restrict__ xb = g_xyz4 + (size_t)b * N;
    const float4 Q = __ldg(&xb[q]);
    const float qs = Q.w;

    float tv[16]; int ti[16];
#pragma unroll
    for (int t = 0; t < 16; ++t) { tv[t] = CUDART_INF_F; ti[t] = 0; }

    const int lo = s << 11;                      // s * 2048

    // ---- seed: first 32 candidates of own range (rolled loop: small I$) ----
#pragma unroll 1
    for (int jj = 0; jj < 32; ++jj) {
        int j = lo + jj;
        float4 p = __ldg(&xb[j]);
        float dot = Q.x * p.x;
        dot = fmaf(Q.y, p.y, dot);
        dot = fmaf(Q.z, p.z, dot);
        float d = fmaf(-2.0f, dot, qs + p.w);
        insert16(tv, ti, d, j);
    }
    float thr = tv[15];

    unsigned addr0 = (unsigned)__cvta_generic_to_shared(&buf[0][0]) + tid * 8u;
    unsigned addr  = addr0;
    const unsigned athr = addr0 + 8u * 1024u;    // slot stride = 128*8 bytes

    // ---- main scan over own 2048-candidate range ----
#pragma unroll 1
    for (int j0 = lo + 32; j0 < lo + 2048; j0 += 8) {
#pragma unroll
        for (int uu = 0; uu < 8; ++uu) {
            int j = j0 + uu;
            float4 p = __ldg(&xb[j]);
            float dot = Q.x * p.x;
            dot = fmaf(Q.y, p.y, dot);
            dot = fmaf(Q.z, p.z, dot);
            float d = fmaf(-2.0f, dot, qs + p.w);
            unsigned long long pk =
                ((unsigned long long)__float_as_uint(d) << 32) | (unsigned)j;
            asm volatile(
                "{\n\t"
                ".reg .pred p;\n\t"
                "setp.lt.f32 p, %1, %2;\n\t"
                "@p st.shared.b64 [%0], %3;\n\t"
                "@p add.u32 %0, %0, 1024;\n\t"
                "}"
                : "+r"(addr) : "f"(d), "f"(thr), "l"(pk) : "memory");
        }
        if (__any_sync(FULL, addr >= athr)) {    // uniform predicate -> plain BRA
            int cnt = (int)((addr - addr0) >> 10);
            int mx  = __reduce_max_sync(FULL, cnt);
#pragma unroll 1
            for (int t = 0; t < mx; ++t) {
                unsigned long long e = buf[t][tid];
                float ed = (t < cnt) ? __uint_as_float((unsigned)(e >> 32))
                                     : CUDART_INF_F;
                int   ej = (int)(unsigned)e;
                insert16(tv, ti, ed, ej);
            }
            addr = addr0;
            thr  = tv[15];
        }
    }
    // ---- final flush ----
    {
        int cnt = (int)((addr - addr0) >> 10);
        int mx  = __reduce_max_sync(FULL, cnt);
#pragma unroll 1
        for (int t = 0; t < mx; ++t) {
            unsigned long long e = buf[t][tid];
            float ed = (t < cnt) ? __uint_as_float((unsigned)(e >> 32))
                                 : CUDART_INF_F;
            int   ej = (int)(unsigned)e;
            insert16(tv, ti, ed, ej);
        }
    }

    // ---- merge split-1 into split-0 (tie -> split-0 = lower index) ----
    if (s == 1) {
#pragma unroll
        for (int t = 0; t < 16; ++t) { mD[u][t] = tv[t]; mI[u][t] = ti[t]; }
    }
    __syncthreads();
    if (s == 0) {
#pragma unroll 1
        for (int t = 0; t < 16; ++t) insert16(tv, ti, mD[u][t], mI[u][t]);
        int* op = g_idx + ((size_t)b * N + q) * KNN;
#pragma unroll
        for (int t = 0; t < 16; ++t) op[t] = ti[t];
    }
}

// ---------------------------------------------------------------------------
// Kernel 3: gather-max over 16 neighbors + transpose to [B][C][N].
// Warp per query (4 queries/warp), 256 threads. Grid: (N/32, B).
// ---------------------------------------------------------------------------
__global__ __launch_bounds__(256) void gather_kernel(float* __restrict__ out)
{
    __shared__ float sout[128][33];

    const int b    = blockIdx.y;
    const int n0   = blockIdx.x * 32;
    const int tid  = threadIdx.x;
    const int w    = tid >> 5;
    const int lane = tid & 31;

    const float* __restrict__ zb = g_zbn + (size_t)b * N * C;

    for (int s = 0; s < 4; ++s) {
        const int ql = w * 4 + s;
        const int n  = n0 + ql;
        int myidx = (lane < 16) ? g_idx[((size_t)b * N + n) * KNN + lane] : 0;

        float m0 = 0.0f, m1 = 0.0f, m2 = 0.0f, m3 = 0.0f;  // post-ReLU >= 0
#pragma unroll
        for (int t = 0; t < KNN; t += 2) {
            int j1 = __shfl_sync(FULL, myidx, t);
            int j2 = __shfl_sync(FULL, myidx, t + 1);
            const float* c1 = zb + ((size_t)j1 << 7);
            const float* c2 = zb + ((size_t)j2 << 7);
            float a0 = c1[lane], a1 = c1[lane + 32], a2 = c1[lane + 64], a3 = c1[lane + 96];
            float b0 = c2[lane], b1 = c2[lane + 32], b2 = c2[lane + 64], b3 = c2[lane + 96];
            m0 = fmaxf(m0, fmaxf(a0, b0));
            m1 = fmaxf(m1, fmaxf(a1, b1));
            m2 = fmaxf(m2, fmaxf(a2, b2));
            m3 = fmaxf(m3, fmaxf(a3, b3));
        }

        sout[lane][ql]      = m0;
        sout[lane + 32][ql] = m1;
        sout[lane + 64][ql] = m2;
        sout[lane + 96][ql] = m3;
    }
    __syncthreads();

    float* ob = out + (size_t)b * C * N + n0;
    for (int i = tid; i < 128 * 32; i += 256) {
        int c = i >> 5, nn = i & 31;
        ob[(size_t)c * N + nn] = sout[c][nn];
    }
}

// ---------------------------------------------------------------------------
extern "C" void kernel_launch(void* const* d_in, const int* in_sizes, int n_in,
                              void* d_out, int out_size)
{
    const float* xyz   = (const float*)d_in[0];
    const float* x     = (const float*)d_in[1];
    const float* W     = (const float*)d_in[2];
    const float* gamma = (const float*)d_in[3];
    const float* beta  = (const float*)d_in[4];
    const float* rmean = (const float*)d_in[5];
    const float* rvar  = (const float*)d_in[6];
    float* out = (float*)d_out;

    prep_kernel<<<B * N / 256, 256>>>(xyz);
    gemm_bn_relu_kernel<<<dim3(N / 64, B), 256>>>(x, W, gamma, beta, rmean, rvar);
    knn_kernel<<<dim3(N / 64, B), 128>>>();
    gather_kernel<<<dim3(N / 32, B), 256>>>(out);
}